// round 4
// baseline (speedup 1.0000x reference)
#include <cuda_runtime.h>
#include <cuda_bf16.h>
#include <math.h>

#define N_NODES 20000
#define N_EDGES 320000
#define F_IN 6
#define HID 128
#define N_CLS 21
#define N_LAYERS 4
#define NUM_G 16
#define ZDIM 272
#define EPS 1e-5f
#define COEFF (-0.5f / ((8.0f/15.0f)*(8.0f/15.0f)))

// ------------- scratch (__device__ globals; no runtime allocation) -------------
__device__ float g_h[N_NODES * HID];        // current node features
__device__ float g_AB[N_NODES * 512];       // [A_f | B_f | A_s | B_s] per node
__device__ float g_e[N_EDGES * NUM_G];      // RBF expansion
__device__ float g_agg[N_NODES * HID];      // aggregated messages
__device__ float g_stats[2 * HID];          // BN sum / sumsq
__device__ int   g_deg[N_NODES];
__device__ int   g_rowstart[N_NODES + 1];
__device__ int   g_cursor[N_NODES];
__device__ int   g_ssrc[N_EDGES];
__device__ int   g_seid[N_EDGES];

__device__ __forceinline__ float sigm(float x) { return 1.f / (1.f + __expf(-x)); }
__device__ __forceinline__ float splus(float x) { return x > 20.f ? x : log1pf(__expf(x)); }

// ------------- tiny utility kernels -------------
__global__ void k_zero_int(int* p, int n) {
    int i = blockIdx.x * blockDim.x + threadIdx.x;
    if (i < n) p[i] = 0;
}
__global__ void k_zero_f(float* p, int n) {
    int i = blockIdx.x * blockDim.x + threadIdx.x;
    if (i < n) p[i] = 0.f;
}

// node embedding: h = x @ W_node + b_node   (x: [N,6], W: [6,128])
__global__ __launch_bounds__(256) void k_embed(const float* __restrict__ x,
                                               const float* __restrict__ W,
                                               const float* __restrict__ b) {
    int t = blockIdx.x * blockDim.x + threadIdx.x;
    if (t >= N_NODES * HID) return;
    int n = t >> 7, c = t & 127;
    float acc = b[c];
    #pragma unroll
    for (int k = 0; k < F_IN; k++) acc += x[n * F_IN + k] * W[k * HID + c];
    g_h[t] = acc;
}

// RBF expansion
__global__ __launch_bounds__(256) void k_rbf(const float* __restrict__ dist) {
    int t = blockIdx.x * blockDim.x + threadIdx.x;
    if (t >= N_EDGES * NUM_G) return;
    int e = t >> 4, k = t & 15;
    float u = dist[e] - (float)k * (8.0f / 15.0f);
    g_e[t] = __expf(COEFF * u * u);
}

// histogram of dst
__global__ __launch_bounds__(256) void k_hist(const int* __restrict__ ei) {
    int i = blockIdx.x * blockDim.x + threadIdx.x;
    if (i >= N_EDGES) return;
    atomicAdd(&g_deg[ei[N_EDGES + i]], 1);
}

// single-block exclusive scan over degrees -> rowstart, cursor
__global__ __launch_bounds__(1024) void k_scan() {
    __shared__ int s[1024];
    __shared__ int carry;
    if (threadIdx.x == 0) carry = 0;
    __syncthreads();
    for (int base = 0; base < N_NODES; base += 1024) {
        int i = base + threadIdx.x;
        int v = (i < N_NODES) ? g_deg[i] : 0;
        s[threadIdx.x] = v;
        __syncthreads();
        for (int off = 1; off < 1024; off <<= 1) {
            int t = (threadIdx.x >= off) ? s[threadIdx.x - off] : 0;
            __syncthreads();
            s[threadIdx.x] += t;
            __syncthreads();
        }
        int c = carry;
        if (i < N_NODES) {
            g_rowstart[i + 1] = c + s[threadIdx.x];
            g_cursor[i] = c + s[threadIdx.x] - v;
        }
        int total = s[1023];
        __syncthreads();
        if (threadIdx.x == 0) carry = c + total;
        __syncthreads();
    }
    if (threadIdx.x == 0) g_rowstart[0] = 0;
}

// scatter edges into CSR buckets
__global__ __launch_bounds__(256) void k_scatter(const int* __restrict__ ei) {
    int i = blockIdx.x * blockDim.x + threadIdx.x;
    if (i >= N_EDGES) return;
    int dst = ei[N_EDGES + i];
    int pos = atomicAdd(&g_cursor[dst], 1);
    g_ssrc[pos] = ei[i];
    g_seid[pos] = i;
}

// ------------- node GEMM: AB = h @ Wcat + bias -------------
// Wcat col groups: [0,128)=Wf rows 0..127 (+bf) | [128,256)=Wf rows 128..255 |
//                  [256,384)=Ws rows 0..127 (+bs) | [384,512)=Ws rows 128..255
#define TM 128
#define TN 64
#define TK 64
__global__ __launch_bounds__(256) void k_gemm(const float* __restrict__ Wf,
                                              const float* __restrict__ Ws,
                                              const float* __restrict__ bf,
                                              const float* __restrict__ bs) {
    __shared__ float As[TK][TM + 4];
    __shared__ float Bs[TK][TN];
    int tid = threadIdx.x;
    int m0 = blockIdx.x * TM;
    int jb = blockIdx.y;
    int g = jb >> 1;
    const float* Wsrc = (g < 2) ? Wf : Ws;
    int rowoff = (g & 1) * 128;
    int coloff = (jb & 1) * 64;
    int tx = tid & 15, ty = tid >> 4;

    float C[8][4];
    #pragma unroll
    for (int i = 0; i < 8; i++)
        #pragma unroll
        for (int j = 0; j < 4; j++) C[i][j] = 0.f;

    int lm = tid & 127;
    int lkq = tid >> 7;
    int bk = tid >> 4;
    int bj = (tid & 15) * 4;

    for (int kc = 0; kc < HID; kc += TK) {
        int gm = m0 + lm;
        #pragma unroll
        for (int f = 0; f < 8; f++) {
            int k = lkq * 32 + f * 4;
            float4 v = make_float4(0.f, 0.f, 0.f, 0.f);
            if (gm < N_NODES) v = *(const float4*)&g_h[gm * HID + kc + k];
            As[k + 0][lm] = v.x; As[k + 1][lm] = v.y;
            As[k + 2][lm] = v.z; As[k + 3][lm] = v.w;
        }
        #pragma unroll
        for (int r = 0; r < 4; r++) {
            int k = bk + r * 16;
            *(float4*)&Bs[k][bj] =
                *(const float4*)&Wsrc[(rowoff + kc + k) * HID + coloff + bj];
        }
        __syncthreads();
        #pragma unroll
        for (int k = 0; k < TK; k++) {
            float4 b = *(float4*)&Bs[k][tx * 4];
            float4 a0 = *(float4*)&As[k][ty * 8];
            float4 a1 = *(float4*)&As[k][ty * 8 + 4];
            float a[8] = {a0.x, a0.y, a0.z, a0.w, a1.x, a1.y, a1.z, a1.w};
            #pragma unroll
            for (int i = 0; i < 8; i++) {
                C[i][0] += a[i] * b.x;
                C[i][1] += a[i] * b.y;
                C[i][2] += a[i] * b.z;
                C[i][3] += a[i] * b.w;
            }
        }
        __syncthreads();
    }
    float4 bias = make_float4(0.f, 0.f, 0.f, 0.f);
    if (g == 0) bias = *(const float4*)&bf[coloff + tx * 4];
    else if (g == 2) bias = *(const float4*)&bs[coloff + tx * 4];
    #pragma unroll
    for (int i = 0; i < 8; i++) {
        int gm = m0 + ty * 8 + i;
        if (gm < N_NODES) {
            float4 o = make_float4(C[i][0] + bias.x, C[i][1] + bias.y,
                                   C[i][2] + bias.z, C[i][3] + bias.w);
            *(float4*)&g_AB[gm * 512 + jb * 64 + tx * 4] = o;
        }
    }
}

// ------------- per-node aggregation (warp per node) + BN partial stats -------------
__global__ __launch_bounds__(256) void k_agg(const float* __restrict__ Wfe,
                                             const float* __restrict__ Wse) {
    __shared__ float4 sWf[NUM_G][32];
    __shared__ float4 sWs[NUM_G][32];
    __shared__ float sSum[HID], sSq[HID];
    int tid = threadIdx.x;
    for (int i = tid; i < NUM_G * 32; i += 256) {
        ((float4*)sWf)[i] = ((const float4*)Wfe)[i];
        ((float4*)sWs)[i] = ((const float4*)Wse)[i];
    }
    if (tid < HID) { sSum[tid] = 0.f; sSq[tid] = 0.f; }
    __syncthreads();

    int warp = tid >> 5, lane = tid & 31;
    int node = blockIdx.x * 8 + warp;
    float4 acc = make_float4(0.f, 0.f, 0.f, 0.f);
    if (node < N_NODES) {
        float4 Af = *(const float4*)&g_AB[node * 512 + lane * 4];
        float4 Asv = *(const float4*)&g_AB[node * 512 + 256 + lane * 4];
        int p0 = g_rowstart[node], p1 = g_rowstart[node + 1];
        for (int p = p0; p < p1; p++) {
            int src = g_ssrc[p];
            int eid = g_seid[p];
            float ev = g_e[eid * NUM_G + (lane & 15)];
            float4 bf4 = *(const float4*)&g_AB[src * 512 + 128 + lane * 4];
            float4 bs4 = *(const float4*)&g_AB[src * 512 + 384 + lane * 4];
            float4 f = make_float4(Af.x + bf4.x, Af.y + bf4.y, Af.z + bf4.z, Af.w + bf4.w);
            float4 s = make_float4(Asv.x + bs4.x, Asv.y + bs4.y, Asv.z + bs4.z, Asv.w + bs4.w);
            #pragma unroll
            for (int k = 0; k < NUM_G; k++) {
                float ek = __shfl_sync(0xffffffffu, ev, k);
                float4 wf = sWf[k][lane];
                float4 ws = sWs[k][lane];
                f.x += ek * wf.x; f.y += ek * wf.y; f.z += ek * wf.z; f.w += ek * wf.w;
                s.x += ek * ws.x; s.y += ek * ws.y; s.z += ek * ws.z; s.w += ek * ws.w;
            }
            acc.x += sigm(f.x) * splus(s.x);
            acc.y += sigm(f.y) * splus(s.y);
            acc.z += sigm(f.z) * splus(s.z);
            acc.w += sigm(f.w) * splus(s.w);
        }
        *(float4*)&g_agg[node * HID + lane * 4] = acc;
    }
    int c = lane * 4;
    atomicAdd(&sSum[c + 0], acc.x); atomicAdd(&sSq[c + 0], acc.x * acc.x);
    atomicAdd(&sSum[c + 1], acc.y); atomicAdd(&sSq[c + 1], acc.y * acc.y);
    atomicAdd(&sSum[c + 2], acc.z); atomicAdd(&sSq[c + 2], acc.z * acc.z);
    atomicAdd(&sSum[c + 3], acc.w); atomicAdd(&sSq[c + 3], acc.w * acc.w);
    __syncthreads();
    if (tid < HID) {
        atomicAdd(&g_stats[tid], sSum[tid]);
        atomicAdd(&g_stats[HID + tid], sSq[tid]);
    }
}

// ------------- BN + residual + LN + ReLU + residual (warp per node) -------------
__global__ __launch_bounds__(256) void k_norm(const float* __restrict__ bng,
                                              const float* __restrict__ bnb,
                                              const float* __restrict__ lng,
                                              const float* __restrict__ lnb) {
    int warp = threadIdx.x >> 5, lane = threadIdx.x & 31;
    int node = blockIdx.x * 8 + warp;
    if (node >= N_NODES) return;
    const float invN = 1.f / (float)N_NODES;
    float4 a = *(const float4*)&g_agg[node * HID + lane * 4];
    float4 hv = *(const float4*)&g_h[node * HID + lane * 4];
    float av[4] = {a.x, a.y, a.z, a.w};
    float hvv[4] = {hv.x, hv.y, hv.z, hv.w};
    float c[4];
    #pragma unroll
    for (int i = 0; i < 4; i++) {
        int ch = lane * 4 + i;
        float mu = g_stats[ch] * invN;
        float var = g_stats[HID + ch] * invN - mu * mu;
        float an = (av[i] - mu) * rsqrtf(var + EPS) * bng[ch] + bnb[ch];
        c[i] = an + hvv[i];
    }
    float s1 = c[0] + c[1] + c[2] + c[3];
    float s2 = c[0]*c[0] + c[1]*c[1] + c[2]*c[2] + c[3]*c[3];
    #pragma unroll
    for (int off = 16; off > 0; off >>= 1) {
        s1 += __shfl_xor_sync(0xffffffffu, s1, off);
        s2 += __shfl_xor_sync(0xffffffffu, s2, off);
    }
    float m = s1 * (1.f / HID);
    float r = rsqrtf(s2 * (1.f / HID) - m * m + EPS);
    float4 o;
    float out[4];
    #pragma unroll
    for (int i = 0; i < 4; i++) {
        int ch = lane * 4 + i;
        out[i] = fmaxf((c[i] - m) * r * lng[ch] + lnb[ch], 0.f) + hvv[i];
    }
    o = make_float4(out[0], out[1], out[2], out[3]);
    *(float4*)&g_h[node * HID + lane * 4] = o;
}

// ------------- final LN + FC (warp per node) -------------
__global__ __launch_bounds__(256) void k_out(const float* __restrict__ lg,
                                             const float* __restrict__ lb,
                                             const float* __restrict__ Wfc,
                                             const float* __restrict__ bfc,
                                             float* __restrict__ out) {
    int warp = threadIdx.x >> 5, lane = threadIdx.x & 31;
    int node = blockIdx.x * 8 + warp;
    if (node >= N_NODES) return;
    float4 hv = *(const float4*)&g_h[node * HID + lane * 4];
    float h[4] = {hv.x, hv.y, hv.z, hv.w};
    float s1 = h[0] + h[1] + h[2] + h[3];
    float s2 = h[0]*h[0] + h[1]*h[1] + h[2]*h[2] + h[3]*h[3];
    #pragma unroll
    for (int off = 16; off > 0; off >>= 1) {
        s1 += __shfl_xor_sync(0xffffffffu, s1, off);
        s2 += __shfl_xor_sync(0xffffffffu, s2, off);
    }
    float m = s1 * (1.f / HID);
    float r = rsqrtf(s2 * (1.f / HID) - m * m + EPS);
    float hn[4];
    #pragma unroll
    for (int i = 0; i < 4; i++) {
        int ch = lane * 4 + i;
        hn[i] = (h[i] - m) * r * lg[ch] + lb[ch];
    }
    for (int cidx = 0; cidx < N_CLS; cidx++) {
        float p = hn[0] * Wfc[(lane * 4 + 0) * N_CLS + cidx]
                + hn[1] * Wfc[(lane * 4 + 1) * N_CLS + cidx]
                + hn[2] * Wfc[(lane * 4 + 2) * N_CLS + cidx]
                + hn[3] * Wfc[(lane * 4 + 3) * N_CLS + cidx];
        #pragma unroll
        for (int off = 16; off > 0; off >>= 1)
            p += __shfl_xor_sync(0xffffffffu, p, off);
        if (lane == 0) out[node * N_CLS + cidx] = p + bfc[cidx];
    }
}

// ------------- launch -------------
extern "C" void kernel_launch(void* const* d_in, const int* in_sizes, int n_in,
                              void* d_out, int out_size) {
    const float* x        = (const float*)d_in[0];
    const int*   ei       = (const int*)d_in[1];
    const float* dist     = (const float*)d_in[2];
    const float* W_node   = (const float*)d_in[3];
    const float* b_node   = (const float*)d_in[4];
    const float* Wf       = (const float*)d_in[5];
    const float* bf       = (const float*)d_in[6];
    const float* Ws       = (const float*)d_in[7];
    const float* bs       = (const float*)d_in[8];
    const float* bn_g     = (const float*)d_in[9];
    const float* bn_b     = (const float*)d_in[10];
    const float* ln_g     = (const float*)d_in[11];
    const float* ln_b     = (const float*)d_in[12];
    const float* lnout_g  = (const float*)d_in[13];
    const float* lnout_b  = (const float*)d_in[14];
    const float* W_fc     = (const float*)d_in[15];
    const float* b_fc     = (const float*)d_in[16];
    float* out = (float*)d_out;

    int* deg_p;        cudaGetSymbolAddress((void**)&deg_p, g_deg);
    float* stats_p;    cudaGetSymbolAddress((void**)&stats_p, g_stats);

    k_zero_int<<<(N_NODES + 255) / 256, 256>>>(deg_p, N_NODES);
    k_embed<<<(N_NODES * HID + 255) / 256, 256>>>(x, W_node, b_node);
    k_rbf<<<(N_EDGES * NUM_G + 255) / 256, 256>>>(dist);
    k_hist<<<(N_EDGES + 255) / 256, 256>>>(ei);
    k_scan<<<1, 1024>>>();
    k_scatter<<<(N_EDGES + 255) / 256, 256>>>(ei);

    dim3 ggrid((N_NODES + TM - 1) / TM, 512 / TN);
    int nblocks = (N_NODES + 7) / 8;
    for (int l = 0; l < N_LAYERS; l++) {
        const float* Wfl = Wf + (size_t)l * ZDIM * HID;
        const float* Wsl = Ws + (size_t)l * ZDIM * HID;
        k_zero_f<<<1, 256>>>(stats_p, 2 * HID);
        k_gemm<<<ggrid, 256>>>(Wfl, Wsl, bf + l * HID, bs + l * HID);
        k_agg<<<nblocks, 256>>>(Wfl + 256 * HID, Wsl + 256 * HID);
        k_norm<<<nblocks, 256>>>(bn_g + l * HID, bn_b + l * HID,
                                 ln_g + l * HID, ln_b + l * HID);
    }
    k_out<<<nblocks, 256>>>(lnout_g, lnout_b, W_fc, b_fc, out);
}

// round 6
// speedup vs baseline: 1.0249x; 1.0249x over previous
#include <cuda_runtime.h>
#include <cuda_bf16.h>
#include <math.h>

#define N_NODES 20000
#define N_EDGES 320000
#define F_IN 6
#define HID 128
#define N_CLS 21
#define N_LAYERS 4
#define NUM_G 16
#define ZDIM 272
#define EPS 1e-5f
#define COEFF (-0.5f / ((8.0f/15.0f)*(8.0f/15.0f)))

// ------------- scratch (__device__ globals; no runtime allocation) -------------
__device__ float g_h[N_NODES * HID];        // current node features
__device__ float g_AB[N_NODES * 512];       // [A_f | B_f | A_s | B_s] per node
__device__ float g_e[N_EDGES * NUM_G];      // RBF expansion
__device__ float g_agg[N_NODES * HID];      // aggregated messages
__device__ float g_stats[2 * HID];          // BN sum / sumsq
__device__ int   g_deg[N_NODES];
__device__ int   g_rowstart[N_NODES + 1];
__device__ int   g_cursor[N_NODES];
__device__ int   g_ssrc[N_EDGES];
__device__ int   g_seid[N_EDGES];

// fast sigmoid: MUFU.EX2 + FADD + MUFU.RCP
__device__ __forceinline__ float sigm(float x) {
    return __fdividef(1.f, 1.f + __expf(-x));
}
// fast softplus: max(x,0) + log(1+exp(-|x|))  -> 2 MUFU + few ALU
__device__ __forceinline__ float splus(float x) {
    float e = __expf(-fabsf(x));
    return fmaxf(x, 0.f) + __logf(1.f + e);
}

// ------------- tiny utility kernels -------------
__global__ void k_zero_int(int* p, int n) {
    int i = blockIdx.x * blockDim.x + threadIdx.x;
    if (i < n) p[i] = 0;
}
__global__ void k_zero_f(float* p, int n) {
    int i = blockIdx.x * blockDim.x + threadIdx.x;
    if (i < n) p[i] = 0.f;
}

// node embedding: h = x @ W_node + b_node   (x: [N,6], W: [6,128])
__global__ __launch_bounds__(256) void k_embed(const float* __restrict__ x,
                                               const float* __restrict__ W,
                                               const float* __restrict__ b) {
    int t = blockIdx.x * blockDim.x + threadIdx.x;
    if (t >= N_NODES * HID) return;
    int n = t >> 7, c = t & 127;
    float acc = b[c];
    #pragma unroll
    for (int k = 0; k < F_IN; k++) acc += x[n * F_IN + k] * W[k * HID + c];
    g_h[t] = acc;
}

// RBF expansion
__global__ __launch_bounds__(256) void k_rbf(const float* __restrict__ dist) {
    int t = blockIdx.x * blockDim.x + threadIdx.x;
    if (t >= N_EDGES * NUM_G) return;
    int e = t >> 4, k = t & 15;
    float u = dist[e] - (float)k * (8.0f / 15.0f);
    g_e[t] = __expf(COEFF * u * u);
}

// histogram of dst
__global__ __launch_bounds__(256) void k_hist(const int* __restrict__ ei) {
    int i = blockIdx.x * blockDim.x + threadIdx.x;
    if (i >= N_EDGES) return;
    atomicAdd(&g_deg[ei[N_EDGES + i]], 1);
}

// single-block exclusive scan over degrees -> rowstart, cursor
__global__ __launch_bounds__(1024) void k_scan() {
    __shared__ int s[1024];
    __shared__ int carry;
    if (threadIdx.x == 0) carry = 0;
    __syncthreads();
    for (int base = 0; base < N_NODES; base += 1024) {
        int i = base + threadIdx.x;
        int v = (i < N_NODES) ? g_deg[i] : 0;
        s[threadIdx.x] = v;
        __syncthreads();
        for (int off = 1; off < 1024; off <<= 1) {
            int t = (threadIdx.x >= off) ? s[threadIdx.x - off] : 0;
            __syncthreads();
            s[threadIdx.x] += t;
            __syncthreads();
        }
        int c = carry;
        if (i < N_NODES) {
            g_rowstart[i + 1] = c + s[threadIdx.x];
            g_cursor[i] = c + s[threadIdx.x] - v;
        }
        int total = s[1023];
        __syncthreads();
        if (threadIdx.x == 0) carry = c + total;
        __syncthreads();
    }
    if (threadIdx.x == 0) g_rowstart[0] = 0;
}

// scatter edges into CSR buckets
__global__ __launch_bounds__(256) void k_scatter(const int* __restrict__ ei) {
    int i = blockIdx.x * blockDim.x + threadIdx.x;
    if (i >= N_EDGES) return;
    int dst = ei[N_EDGES + i];
    int pos = atomicAdd(&g_cursor[dst], 1);
    g_ssrc[pos] = ei[i];
    g_seid[pos] = i;
}

// ------------- node GEMM: AB = h @ Wcat + bias -------------
// 128x128 block tile, 8x8 microtile, TK=32.
// Output col groups (128 wide each):
//   g=0: Wf rows 0..127 (+bf) | g=1: Wf rows 128..255 |
//   g=2: Ws rows 0..127 (+bs) | g=3: Ws rows 128..255
#define GTM 128
#define GTN 128
#define GTK 32
__global__ __launch_bounds__(256) void k_gemm(const float* __restrict__ Wf,
                                              const float* __restrict__ Ws,
                                              const float* __restrict__ bf,
                                              const float* __restrict__ bs) {
    __shared__ float As[GTK][GTM + 4];
    __shared__ float Bs[GTK][GTN];
    int tid = threadIdx.x;
    int m0 = blockIdx.x * GTM;
    int g = blockIdx.y;  // 0..3
    const float* __restrict__ Wsrc = (g < 2) ? Wf : Ws;
    int rowoff = (g & 1) * 128;
    int tx = tid & 15, ty = tid >> 4;

    float C[8][8];
    #pragma unroll
    for (int i = 0; i < 8; i++)
        #pragma unroll
        for (int j = 0; j < 8; j++) C[i][j] = 0.f;

    int lm = tid & 127;
    int lk = (tid >> 7) * 16;   // 0 or 16
    int bn4 = (tid & 31) * 4;
    int bk0 = tid >> 5;         // 0..7

    for (int kc = 0; kc < HID; kc += GTK) {
        int gm = m0 + lm;
        #pragma unroll
        for (int f = 0; f < 4; f++) {
            int k = lk + f * 4;
            float4 v = make_float4(0.f, 0.f, 0.f, 0.f);
            if (gm < N_NODES) v = *(const float4*)&g_h[gm * HID + kc + k];
            As[k + 0][lm] = v.x; As[k + 1][lm] = v.y;
            As[k + 2][lm] = v.z; As[k + 3][lm] = v.w;
        }
        #pragma unroll
        for (int f = 0; f < 4; f++) {
            int k = bk0 + f * 8;
            *(float4*)&Bs[k][bn4] =
                *(const float4*)&Wsrc[(rowoff + kc + k) * HID + bn4];
        }
        __syncthreads();
        #pragma unroll
        for (int k = 0; k < GTK; k++) {
            float a[8], b[8];
            *(float4*)(a + 0) = *(float4*)&As[k][ty * 8];
            *(float4*)(a + 4) = *(float4*)&As[k][ty * 8 + 4];
            *(float4*)(b + 0) = *(float4*)&Bs[k][tx * 8];
            *(float4*)(b + 4) = *(float4*)&Bs[k][tx * 8 + 4];
            #pragma unroll
            for (int i = 0; i < 8; i++)
                #pragma unroll
                for (int j = 0; j < 8; j++) C[i][j] += a[i] * b[j];
        }
        __syncthreads();
    }

    float bias[8];
    #pragma unroll
    for (int j = 0; j < 8; j++) bias[j] = 0.f;
    if (g == 0) {
        *(float4*)(bias + 0) = *(const float4*)&bf[tx * 8];
        *(float4*)(bias + 4) = *(const float4*)&bf[tx * 8 + 4];
    } else if (g == 2) {
        *(float4*)(bias + 0) = *(const float4*)&bs[tx * 8];
        *(float4*)(bias + 4) = *(const float4*)&bs[tx * 8 + 4];
    }
    #pragma unroll
    for (int i = 0; i < 8; i++) {
        int gm = m0 + ty * 8 + i;
        if (gm < N_NODES) {
            float o[8];
            #pragma unroll
            for (int j = 0; j < 8; j++) o[j] = C[i][j] + bias[j];
            *(float4*)&g_AB[gm * 512 + g * 128 + tx * 8]     = *(float4*)(o + 0);
            *(float4*)&g_AB[gm * 512 + g * 128 + tx * 8 + 4] = *(float4*)(o + 4);
        }
    }
}

// ------------- per-node aggregation (warp per node) + BN partial stats -------------
__global__ __launch_bounds__(256) void k_agg(const float* __restrict__ Wfe,
                                             const float* __restrict__ Wse) {
    __shared__ float4 sWf[NUM_G][32];
    __shared__ float4 sWs[NUM_G][32];
    __shared__ float sSum[HID], sSq[HID];
    int tid = threadIdx.x;
    for (int i = tid; i < NUM_G * 32; i += 256) {
        ((float4*)sWf)[i] = ((const float4*)Wfe)[i];
        ((float4*)sWs)[i] = ((const float4*)Wse)[i];
    }
    if (tid < HID) { sSum[tid] = 0.f; sSq[tid] = 0.f; }
    __syncthreads();

    int warp = tid >> 5, lane = tid & 31;
    int node = blockIdx.x * 8 + warp;
    float4 acc = make_float4(0.f, 0.f, 0.f, 0.f);
    if (node < N_NODES) {
        float4 Af = *(const float4*)&g_AB[node * 512 + lane * 4];
        float4 Asv = *(const float4*)&g_AB[node * 512 + 256 + lane * 4];
        int p0 = g_rowstart[node], p1 = g_rowstart[node + 1];
        int src = 0, eid = 0;
        if (p0 < p1) { src = g_ssrc[p0]; eid = g_seid[p0]; }
        for (int p = p0; p < p1; p++) {
            // prefetch next edge's indices early to overlap latency
            int nsrc = src, neid = eid;
            if (p + 1 < p1) { nsrc = g_ssrc[p + 1]; neid = g_seid[p + 1]; }
            float ev = g_e[eid * NUM_G + (lane & 15)];
            float4 bf4 = *(const float4*)&g_AB[src * 512 + 128 + lane * 4];
            float4 bs4 = *(const float4*)&g_AB[src * 512 + 384 + lane * 4];
            src = nsrc; eid = neid;
            float4 f = make_float4(Af.x + bf4.x, Af.y + bf4.y, Af.z + bf4.z, Af.w + bf4.w);
            float4 s = make_float4(Asv.x + bs4.x, Asv.y + bs4.y, Asv.z + bs4.z, Asv.w + bs4.w);
            #pragma unroll
            for (int k = 0; k < NUM_G; k++) {
                float ek = __shfl_sync(0xffffffffu, ev, k);
                float4 wf = sWf[k][lane];
                float4 ws = sWs[k][lane];
                f.x += ek * wf.x; f.y += ek * wf.y; f.z += ek * wf.z; f.w += ek * wf.w;
                s.x += ek * ws.x; s.y += ek * ws.y; s.z += ek * ws.z; s.w += ek * ws.w;
            }
            acc.x += sigm(f.x) * splus(s.x);
            acc.y += sigm(f.y) * splus(s.y);
            acc.z += sigm(f.z) * splus(s.z);
            acc.w += sigm(f.w) * splus(s.w);
        }
        *(float4*)&g_agg[node * HID + lane * 4] = acc;
    }
    int c = lane * 4;
    atomicAdd(&sSum[c + 0], acc.x); atomicAdd(&sSq[c + 0], acc.x * acc.x);
    atomicAdd(&sSum[c + 1], acc.y); atomicAdd(&sSq[c + 1], acc.y * acc.y);
    atomicAdd(&sSum[c + 2], acc.z); atomicAdd(&sSq[c + 2], acc.z * acc.z);
    atomicAdd(&sSum[c + 3], acc.w); atomicAdd(&sSq[c + 3], acc.w * acc.w);
    __syncthreads();
    if (tid < HID) {
        atomicAdd(&g_stats[tid], sSum[tid]);
        atomicAdd(&g_stats[HID + tid], sSq[tid]);
    }
}

// ------------- BN + residual + LN + ReLU + residual (warp per node) -------------
__global__ __launch_bounds__(256) void k_norm(const float* __restrict__ bng,
                                              const float* __restrict__ bnb,
                                              const float* __restrict__ lng,
                                              const float* __restrict__ lnb) {
    int warp = threadIdx.x >> 5, lane = threadIdx.x & 31;
    int node = blockIdx.x * 8 + warp;
    if (node >= N_NODES) return;
    const float invN = 1.f / (float)N_NODES;
    float4 a = *(const float4*)&g_agg[node * HID + lane * 4];
    float4 hv = *(const float4*)&g_h[node * HID + lane * 4];
    float av[4] = {a.x, a.y, a.z, a.w};
    float hvv[4] = {hv.x, hv.y, hv.z, hv.w};
    float c[4];
    #pragma unroll
    for (int i = 0; i < 4; i++) {
        int ch = lane * 4 + i;
        float mu = g_stats[ch] * invN;
        float var = g_stats[HID + ch] * invN - mu * mu;
        float an = (av[i] - mu) * rsqrtf(var + EPS) * bng[ch] + bnb[ch];
        c[i] = an + hvv[i];
    }
    float s1 = c[0] + c[1] + c[2] + c[3];
    float s2 = c[0]*c[0] + c[1]*c[1] + c[2]*c[2] + c[3]*c[3];
    #pragma unroll
    for (int off = 16; off > 0; off >>= 1) {
        s1 += __shfl_xor_sync(0xffffffffu, s1, off);
        s2 += __shfl_xor_sync(0xffffffffu, s2, off);
    }
    float m = s1 * (1.f / HID);
    float r = rsqrtf(s2 * (1.f / HID) - m * m + EPS);
    float out[4];
    #pragma unroll
    for (int i = 0; i < 4; i++) {
        int ch = lane * 4 + i;
        out[i] = fmaxf((c[i] - m) * r * lng[ch] + lnb[ch], 0.f) + hvv[i];
    }
    float4 o = make_float4(out[0], out[1], out[2], out[3]);
    *(float4*)&g_h[node * HID + lane * 4] = o;
}

// ------------- final LN + FC (warp per node) -------------
__global__ __launch_bounds__(256) void k_out(const float* __restrict__ lg,
                                             const float* __restrict__ lb,
                                             const float* __restrict__ Wfc,
                                             const float* __restrict__ bfc,
                                             float* __restrict__ out) {
    int warp = threadIdx.x >> 5, lane = threadIdx.x & 31;
    int node = blockIdx.x * 8 + warp;
    if (node >= N_NODES) return;
    float4 hv = *(const float4*)&g_h[node * HID + lane * 4];
    float h[4] = {hv.x, hv.y, hv.z, hv.w};
    float s1 = h[0] + h[1] + h[2] + h[3];
    float s2 = h[0]*h[0] + h[1]*h[1] + h[2]*h[2] + h[3]*h[3];
    #pragma unroll
    for (int off = 16; off > 0; off >>= 1) {
        s1 += __shfl_xor_sync(0xffffffffu, s1, off);
        s2 += __shfl_xor_sync(0xffffffffu, s2, off);
    }
    float m = s1 * (1.f / HID);
    float r = rsqrtf(s2 * (1.f / HID) - m * m + EPS);
    float hn[4];
    #pragma unroll
    for (int i = 0; i < 4; i++) {
        int ch = lane * 4 + i;
        hn[i] = (h[i] - m) * r * lg[ch] + lb[ch];
    }
    for (int cidx = 0; cidx < N_CLS; cidx++) {
        float p = hn[0] * Wfc[(lane * 4 + 0) * N_CLS + cidx]
                + hn[1] * Wfc[(lane * 4 + 1) * N_CLS + cidx]
                + hn[2] * Wfc[(lane * 4 + 2) * N_CLS + cidx]
                + hn[3] * Wfc[(lane * 4 + 3) * N_CLS + cidx];
        #pragma unroll
        for (int off = 16; off > 0; off >>= 1)
            p += __shfl_xor_sync(0xffffffffu, p, off);
        if (lane == 0) out[node * N_CLS + cidx] = p + bfc[cidx];
    }
}

// ------------- launch -------------
extern "C" void kernel_launch(void* const* d_in, const int* in_sizes, int n_in,
                              void* d_out, int out_size) {
    const float* x        = (const float*)d_in[0];
    const int*   ei       = (const int*)d_in[1];
    const float* dist     = (const float*)d_in[2];
    const float* W_node   = (const float*)d_in[3];
    const float* b_node   = (const float*)d_in[4];
    const float* Wf       = (const float*)d_in[5];
    const float* bf       = (const float*)d_in[6];
    const float* Ws       = (const float*)d_in[7];
    const float* bs       = (const float*)d_in[8];
    const float* bn_g     = (const float*)d_in[9];
    const float* bn_b     = (const float*)d_in[10];
    const float* ln_g     = (const float*)d_in[11];
    const float* ln_b     = (const float*)d_in[12];
    const float* lnout_g  = (const float*)d_in[13];
    const float* lnout_b  = (const float*)d_in[14];
    const float* W_fc     = (const float*)d_in[15];
    const float* b_fc     = (const float*)d_in[16];
    float* out = (float*)d_out;

    int* deg_p;        cudaGetSymbolAddress((void**)&deg_p, g_deg);
    float* stats_p;    cudaGetSymbolAddress((void**)&stats_p, g_stats);

    k_zero_int<<<(N_NODES + 255) / 256, 256>>>(deg_p, N_NODES);
    k_embed<<<(N_NODES * HID + 255) / 256, 256>>>(x, W_node, b_node);
    k_rbf<<<(N_EDGES * NUM_G + 255) / 256, 256>>>(dist);
    k_hist<<<(N_EDGES + 255) / 256, 256>>>(ei);
    k_scan<<<1, 1024>>>();
    k_scatter<<<(N_EDGES + 255) / 256, 256>>>(ei);

    dim3 ggrid((N_NODES + GTM - 1) / GTM, 4);
    int nblocks = (N_NODES + 7) / 8;
    for (int l = 0; l < N_LAYERS; l++) {
        const float* Wfl = Wf + (size_t)l * ZDIM * HID;
        const float* Wsl = Ws + (size_t)l * ZDIM * HID;
        k_zero_f<<<1, 256>>>(stats_p, 2 * HID);
        k_gemm<<<ggrid, 256>>>(Wfl, Wsl, bf + l * HID, bs + l * HID);
        k_agg<<<nblocks, 256>>>(Wfl + 256 * HID, Wsl + 256 * HID);
        k_norm<<<nblocks, 256>>>(bn_g + l * HID, bn_b + l * HID,
                                 ln_g + l * HID, ln_b + l * HID);
    }
    k_out<<<nblocks, 256>>>(lnout_g, lnout_b, W_fc, b_fc, out);
}

// round 8
// speedup vs baseline: 1.4020x; 1.3679x over previous
#include <cuda_runtime.h>
#include <cuda_bf16.h>
#include <math.h>

#define N_NODES 20000
#define N_EDGES 320000
#define F_IN 6
#define HID 128
#define N_CLS 21
#define N_LAYERS 4
#define NUM_G 16
#define ZDIM 272
#define EPS 1e-5f
#define COEFF (-0.5f / ((8.0f/15.0f)*(8.0f/15.0f)))

typedef unsigned long long u64;

// ---- packed fp32x2 helpers (sm_103a FFMA2 path; PTX-only per SASS_QUICKREF) ----
__device__ __forceinline__ u64 pack2(float lo, float hi) {
    u64 r; asm("mov.b64 %0, {%1, %2};" : "=l"(r) : "f"(lo), "f"(hi)); return r;
}
__device__ __forceinline__ void unpack2(u64 v, float& lo, float& hi) {
    asm("mov.b64 {%0, %1}, %2;" : "=f"(lo), "=f"(hi) : "l"(v));
}
__device__ __forceinline__ u64 fma2(u64 a, u64 b, u64 c) {
    u64 d; asm("fma.rn.f32x2 %0, %1, %2, %3;" : "=l"(d) : "l"(a), "l"(b), "l"(c)); return d;
}
__device__ __forceinline__ u64 add2(u64 a, u64 b) {
    u64 d; asm("add.rn.f32x2 %0, %1, %2;" : "=l"(d) : "l"(a), "l"(b)); return d;
}

// ------------- scratch (__device__ globals; no runtime allocation) -------------
__device__ float g_h[N_NODES * HID];        // current node features
__device__ float g_AB[N_NODES * 512];       // [A_f | B_f | A_s | B_s] per node
__device__ float g_e[N_EDGES * NUM_G];      // RBF expansion
__device__ float g_agg[N_NODES * HID];      // aggregated messages
__device__ float g_stats[2 * HID];          // BN sum / sumsq
__device__ int   g_deg[N_NODES];
__device__ int   g_rowstart[N_NODES + 1];
__device__ int   g_cursor[N_NODES];
__device__ int   g_ssrc[N_EDGES];
__device__ int   g_seid[N_EDGES];

__device__ __forceinline__ float sigm(float x) {
    return __fdividef(1.f, 1.f + __expf(-x));
}
__device__ __forceinline__ float splus(float x) {
    float e = __expf(-fabsf(x));
    return fmaxf(x, 0.f) + __logf(1.f + e);
}

// ------------- tiny utility kernels -------------
__global__ void k_zero_int(int* p, int n) {
    int i = blockIdx.x * blockDim.x + threadIdx.x;
    if (i < n) p[i] = 0;
}
__global__ void k_zero_f(float* p, int n) {
    int i = blockIdx.x * blockDim.x + threadIdx.x;
    if (i < n) p[i] = 0.f;
}

// node embedding: h = x @ W_node + b_node   (x: [N,6], W: [6,128])
__global__ __launch_bounds__(256) void k_embed(const float* __restrict__ x,
                                               const float* __restrict__ W,
                                               const float* __restrict__ b) {
    int t = blockIdx.x * blockDim.x + threadIdx.x;
    if (t >= N_NODES * HID) return;
    int n = t >> 7, c = t & 127;
    float acc = b[c];
    #pragma unroll
    for (int k = 0; k < F_IN; k++) acc += x[n * F_IN + k] * W[k * HID + c];
    g_h[t] = acc;
}

// RBF expansion
__global__ __launch_bounds__(256) void k_rbf(const float* __restrict__ dist) {
    int t = blockIdx.x * blockDim.x + threadIdx.x;
    if (t >= N_EDGES * NUM_G) return;
    int e = t >> 4, k = t & 15;
    float u = dist[e] - (float)k * (8.0f / 15.0f);
    g_e[t] = __expf(COEFF * u * u);
}

// histogram of dst
__global__ __launch_bounds__(256) void k_hist(const int* __restrict__ ei) {
    int i = blockIdx.x * blockDim.x + threadIdx.x;
    if (i >= N_EDGES) return;
    atomicAdd(&g_deg[ei[N_EDGES + i]], 1);
}

// single-block exclusive scan over degrees -> rowstart, cursor
__global__ __launch_bounds__(1024) void k_scan() {
    __shared__ int s[1024];
    __shared__ int carry;
    if (threadIdx.x == 0) carry = 0;
    __syncthreads();
    for (int base = 0; base < N_NODES; base += 1024) {
        int i = base + threadIdx.x;
        int v = (i < N_NODES) ? g_deg[i] : 0;
        s[threadIdx.x] = v;
        __syncthreads();
        for (int off = 1; off < 1024; off <<= 1) {
            int t = (threadIdx.x >= off) ? s[threadIdx.x - off] : 0;
            __syncthreads();
            s[threadIdx.x] += t;
            __syncthreads();
        }
        int c = carry;
        if (i < N_NODES) {
            g_rowstart[i + 1] = c + s[threadIdx.x];
            g_cursor[i] = c + s[threadIdx.x] - v;
        }
        int total = s[1023];
        __syncthreads();
        if (threadIdx.x == 0) carry = c + total;
        __syncthreads();
    }
    if (threadIdx.x == 0) g_rowstart[0] = 0;
}

// scatter edges into CSR buckets
__global__ __launch_bounds__(256) void k_scatter(const int* __restrict__ ei) {
    int i = blockIdx.x * blockDim.x + threadIdx.x;
    if (i >= N_EDGES) return;
    int dst = ei[N_EDGES + i];
    int pos = atomicAdd(&g_cursor[dst], 1);
    g_ssrc[pos] = ei[i];
    g_seid[pos] = i;
}

// ------------- node GEMM: AB = h @ Wcat + bias (FFMA2 inner product) -------------
// Output col groups (128 wide each):
//   g=0: Wf rows 0..127 (+bf) | g=1: Wf rows 128..255 |
//   g=2: Ws rows 0..127 (+bs) | g=3: Ws rows 128..255
#define GTM 128
#define GTN 128
#define GTK 32
__global__ __launch_bounds__(256, 2) void k_gemm(const float* __restrict__ Wf,
                                                 const float* __restrict__ Ws,
                                                 const float* __restrict__ bf,
                                                 const float* __restrict__ bs) {
    __shared__ float As[GTK][GTM + 4];
    __shared__ float Bs[GTK][GTN];
    int tid = threadIdx.x;
    int m0 = blockIdx.x * GTM;
    int g = blockIdx.y;  // 0..3
    const float* __restrict__ Wsrc = (g < 2) ? Wf : Ws;
    int rowoff = (g & 1) * 128;
    int tx = tid & 15, ty = tid >> 4;

    u64 C2[8][4];
    #pragma unroll
    for (int i = 0; i < 8; i++)
        #pragma unroll
        for (int j = 0; j < 4; j++) C2[i][j] = 0ull;  // (0.f, 0.f)

    int lm = tid & 127;
    int lk = (tid >> 7) * 16;   // 0 or 16
    int bn4 = (tid & 31) * 4;
    int bk0 = tid >> 5;         // 0..7

    for (int kc = 0; kc < HID; kc += GTK) {
        int gm = m0 + lm;
        #pragma unroll
        for (int f = 0; f < 4; f++) {
            int k = lk + f * 4;
            float4 v = make_float4(0.f, 0.f, 0.f, 0.f);
            if (gm < N_NODES) v = *(const float4*)&g_h[gm * HID + kc + k];
            As[k + 0][lm] = v.x; As[k + 1][lm] = v.y;
            As[k + 2][lm] = v.z; As[k + 3][lm] = v.w;
        }
        #pragma unroll
        for (int f = 0; f < 4; f++) {
            int k = bk0 + f * 8;
            *(float4*)&Bs[k][bn4] =
                *(const float4*)&Wsrc[(rowoff + kc + k) * HID + bn4];
        }
        __syncthreads();
        #pragma unroll
        for (int k = 0; k < GTK; k++) {
            float a[8];
            *(float4*)(a + 0) = *(float4*)&As[k][ty * 8];
            *(float4*)(a + 4) = *(float4*)&As[k][ty * 8 + 4];
            u64 ap[8];
            #pragma unroll
            for (int i = 0; i < 8; i++) ap[i] = pack2(a[i], a[i]);
            ulonglong2 b0 = *(ulonglong2*)&Bs[k][tx * 8];
            ulonglong2 b1 = *(ulonglong2*)&Bs[k][tx * 8 + 4];
            u64 bp[4] = {b0.x, b0.y, b1.x, b1.y};
            #pragma unroll
            for (int i = 0; i < 8; i++)
                #pragma unroll
                for (int j = 0; j < 4; j++)
                    C2[i][j] = fma2(ap[i], bp[j], C2[i][j]);
        }
        __syncthreads();
    }

    float bias[8];
    #pragma unroll
    for (int j = 0; j < 8; j++) bias[j] = 0.f;
    if (g == 0) {
        *(float4*)(bias + 0) = *(const float4*)&bf[tx * 8];
        *(float4*)(bias + 4) = *(const float4*)&bf[tx * 8 + 4];
    } else if (g == 2) {
        *(float4*)(bias + 0) = *(const float4*)&bs[tx * 8];
        *(float4*)(bias + 4) = *(const float4*)&bs[tx * 8 + 4];
    }
    #pragma unroll
    for (int i = 0; i < 8; i++) {
        int gm = m0 + ty * 8 + i;
        if (gm < N_NODES) {
            float o[8];
            #pragma unroll
            for (int j = 0; j < 4; j++) {
                float lo, hi;
                unpack2(C2[i][j], lo, hi);
                o[2 * j] = lo + bias[2 * j];
                o[2 * j + 1] = hi + bias[2 * j + 1];
            }
            *(float4*)&g_AB[gm * 512 + g * 128 + tx * 8]     = *(float4*)(o + 0);
            *(float4*)&g_AB[gm * 512 + g * 128 + tx * 8 + 4] = *(float4*)(o + 4);
        }
    }
}

// ------------- per-node aggregation (warp per node, 4-edge groups, FFMA2) -------------
__global__ __launch_bounds__(256, 2) void k_agg(const float* __restrict__ Wfe,
                                                const float* __restrict__ Wse) {
    __shared__ ulonglong2 sWf[NUM_G][32];   // each [k][lane] = 4 floats of Wf_e row k
    __shared__ ulonglong2 sWs[NUM_G][32];
    __shared__ float sSum[HID], sSq[HID];
    int tid = threadIdx.x;
    for (int i = tid; i < NUM_G * 32; i += 256) {
        ((ulonglong2*)sWf)[i] = ((const ulonglong2*)Wfe)[i];
        ((ulonglong2*)sWs)[i] = ((const ulonglong2*)Wse)[i];
    }
    if (tid < HID) { sSum[tid] = 0.f; sSq[tid] = 0.f; }
    __syncthreads();

    int warp = tid >> 5, lane = tid & 31;
    int node = blockIdx.x * 8 + warp;
    float acc0 = 0.f, acc1 = 0.f, acc2 = 0.f, acc3 = 0.f;
    if (node < N_NODES) {
        ulonglong2 Afp = *(const ulonglong2*)&g_AB[node * 512 + lane * 4];
        ulonglong2 Asp = *(const ulonglong2*)&g_AB[node * 512 + 256 + lane * 4];
        int p0 = g_rowstart[node], p1 = g_rowstart[node + 1];
        int p = p0;
        // ---- groups of 4 edges: weights loaded once per k, applied to all 4 ----
        for (; p + 4 <= p1; p += 4) {
            int src[4], eid[4];
            float ev[4];
            #pragma unroll
            for (int e = 0; e < 4; e++) { src[e] = g_ssrc[p + e]; eid[e] = g_seid[p + e]; }
            #pragma unroll
            for (int e = 0; e < 4; e++) ev[e] = g_e[eid[e] * NUM_G + (lane & 15)];
            u64 f[4][2], s[4][2];
            #pragma unroll
            for (int e = 0; e < 4; e++) {
                ulonglong2 bf4 = *(const ulonglong2*)&g_AB[src[e] * 512 + 128 + lane * 4];
                ulonglong2 bs4 = *(const ulonglong2*)&g_AB[src[e] * 512 + 384 + lane * 4];
                f[e][0] = add2(Afp.x, bf4.x); f[e][1] = add2(Afp.y, bf4.y);
                s[e][0] = add2(Asp.x, bs4.x); s[e][1] = add2(Asp.y, bs4.y);
            }
            #pragma unroll
            for (int k = 0; k < NUM_G; k++) {
                ulonglong2 wf = sWf[k][lane];
                ulonglong2 ws = sWs[k][lane];
                #pragma unroll
                for (int e = 0; e < 4; e++) {
                    float ek = __shfl_sync(0xffffffffu, ev[e], k);
                    u64 ekp = pack2(ek, ek);
                    f[e][0] = fma2(ekp, wf.x, f[e][0]);
                    f[e][1] = fma2(ekp, wf.y, f[e][1]);
                    s[e][0] = fma2(ekp, ws.x, s[e][0]);
                    s[e][1] = fma2(ekp, ws.y, s[e][1]);
                }
            }
            #pragma unroll
            for (int e = 0; e < 4; e++) {
                float f0, f1, f2, f3, s0, s1, s2, s3;
                unpack2(f[e][0], f0, f1); unpack2(f[e][1], f2, f3);
                unpack2(s[e][0], s0, s1); unpack2(s[e][1], s2, s3);
                acc0 += sigm(f0) * splus(s0);
                acc1 += sigm(f1) * splus(s1);
                acc2 += sigm(f2) * splus(s2);
                acc3 += sigm(f3) * splus(s3);
            }
        }
        // ---- tail (0..3 edges) ----
        for (; p < p1; p++) {
            int src = g_ssrc[p], eid = g_seid[p];
            float ev = g_e[eid * NUM_G + (lane & 15)];
            ulonglong2 bf4 = *(const ulonglong2*)&g_AB[src * 512 + 128 + lane * 4];
            ulonglong2 bs4 = *(const ulonglong2*)&g_AB[src * 512 + 384 + lane * 4];
            u64 f0p = add2(Afp.x, bf4.x), f1p = add2(Afp.y, bf4.y);
            u64 s0p = add2(Asp.x, bs4.x), s1p = add2(Asp.y, bs4.y);
            #pragma unroll
            for (int k = 0; k < NUM_G; k++) {
                float ek = __shfl_sync(0xffffffffu, ev, k);
                u64 ekp = pack2(ek, ek);
                ulonglong2 wf = sWf[k][lane];
                ulonglong2 ws = sWs[k][lane];
                f0p = fma2(ekp, wf.x, f0p); f1p = fma2(ekp, wf.y, f1p);
                s0p = fma2(ekp, ws.x, s0p); s1p = fma2(ekp, ws.y, s1p);
            }
            float f0, f1, f2, f3, s0, s1, s2, s3;
            unpack2(f0p, f0, f1); unpack2(f1p, f2, f3);
            unpack2(s0p, s0, s1); unpack2(s1p, s2, s3);
            acc0 += sigm(f0) * splus(s0);
            acc1 += sigm(f1) * splus(s1);
            acc2 += sigm(f2) * splus(s2);
            acc3 += sigm(f3) * splus(s3);
        }
        float4 o = make_float4(acc0, acc1, acc2, acc3);
        *(float4*)&g_agg[node * HID + lane * 4] = o;
    }
    int c = lane * 4;
    atomicAdd(&sSum[c + 0], acc0); atomicAdd(&sSq[c + 0], acc0 * acc0);
    atomicAdd(&sSum[c + 1], acc1); atomicAdd(&sSq[c + 1], acc1 * acc1);
    atomicAdd(&sSum[c + 2], acc2); atomicAdd(&sSq[c + 2], acc2 * acc2);
    atomicAdd(&sSum[c + 3], acc3); atomicAdd(&sSq[c + 3], acc3 * acc3);
    __syncthreads();
    if (tid < HID) {
        atomicAdd(&g_stats[tid], sSum[tid]);
        atomicAdd(&g_stats[HID + tid], sSq[tid]);
    }
}

// ------------- BN + residual + LN + ReLU + residual (warp per node) -------------
__global__ __launch_bounds__(256) void k_norm(const float* __restrict__ bng,
                                              const float* __restrict__ bnb,
                                              const float* __restrict__ lng,
                                              const float* __restrict__ lnb) {
    int warp = threadIdx.x >> 5, lane = threadIdx.x & 31;
    int node = blockIdx.x * 8 + warp;
    if (node >= N_NODES) return;
    const float invN = 1.f / (float)N_NODES;
    float4 a = *(const float4*)&g_agg[node * HID + lane * 4];
    float4 hv = *(const float4*)&g_h[node * HID + lane * 4];
    float av[4] = {a.x, a.y, a.z, a.w};
    float hvv[4] = {hv.x, hv.y, hv.z, hv.w};
    float c[4];
    #pragma unroll
    for (int i = 0; i < 4; i++) {
        int ch = lane * 4 + i;
        float mu = g_stats[ch] * invN;
        float var = g_stats[HID + ch] * invN - mu * mu;
        float an = (av[i] - mu) * rsqrtf(var + EPS) * bng[ch] + bnb[ch];
        c[i] = an + hvv[i];
    }
    float s1 = c[0] + c[1] + c[2] + c[3];
    float s2 = c[0]*c[0] + c[1]*c[1] + c[2]*c[2] + c[3]*c[3];
    #pragma unroll
    for (int off = 16; off > 0; off >>= 1) {
        s1 += __shfl_xor_sync(0xffffffffu, s1, off);
        s2 += __shfl_xor_sync(0xffffffffu, s2, off);
    }
    float m = s1 * (1.f / HID);
    float r = rsqrtf(s2 * (1.f / HID) - m * m + EPS);
    float out[4];
    #pragma unroll
    for (int i = 0; i < 4; i++) {
        int ch = lane * 4 + i;
        out[i] = fmaxf((c[i] - m) * r * lng[ch] + lnb[ch], 0.f) + hvv[i];
    }
    float4 o = make_float4(out[0], out[1], out[2], out[3]);
    *(float4*)&g_h[node * HID + lane * 4] = o;
}

// ------------- final LN + FC (warp per node) -------------
__global__ __launch_bounds__(256) void k_out(const float* __restrict__ lg,
                                             const float* __restrict__ lb,
                                             const float* __restrict__ Wfc,
                                             const float* __restrict__ bfc,
                                             float* __restrict__ out) {
    int warp = threadIdx.x >> 5, lane = threadIdx.x & 31;
    int node = blockIdx.x * 8 + warp;
    if (node >= N_NODES) return;
    float4 hv = *(const float4*)&g_h[node * HID + lane * 4];
    float h[4] = {hv.x, hv.y, hv.z, hv.w};
    float s1 = h[0] + h[1] + h[2] + h[3];
    float s2 = h[0]*h[0] + h[1]*h[1] + h[2]*h[2] + h[3]*h[3];
    #pragma unroll
    for (int off = 16; off > 0; off >>= 1) {
        s1 += __shfl_xor_sync(0xffffffffu, s1, off);
        s2 += __shfl_xor_sync(0xffffffffu, s2, off);
    }
    float m = s1 * (1.f / HID);
    float r = rsqrtf(s2 * (1.f / HID) - m * m + EPS);
    float hn[4];
    #pragma unroll
    for (int i = 0; i < 4; i++) {
        int ch = lane * 4 + i;
        hn[i] = (h[i] - m) * r * lg[ch] + lb[ch];
    }
    for (int cidx = 0; cidx < N_CLS; cidx++) {
        float p = hn[0] * Wfc[(lane * 4 + 0) * N_CLS + cidx]
                + hn[1] * Wfc[(lane * 4 + 1) * N_CLS + cidx]
                + hn[2] * Wfc[(lane * 4 + 2) * N_CLS + cidx]
                + hn[3] * Wfc[(lane * 4 + 3) * N_CLS + cidx];
        #pragma unroll
        for (int off = 16; off > 0; off >>= 1)
            p += __shfl_xor_sync(0xffffffffu, p, off);
        if (lane == 0) out[node * N_CLS + cidx] = p + bfc[cidx];
    }
}

// ------------- launch -------------
extern "C" void kernel_launch(void* const* d_in, const int* in_sizes, int n_in,
                              void* d_out, int out_size) {
    const float* x        = (const float*)d_in[0];
    const int*   ei       = (const int*)d_in[1];
    const float* dist     = (const float*)d_in[2];
    const float* W_node   = (const float*)d_in[3];
    const float* b_node   = (const float*)d_in[4];
    const float* Wf       = (const float*)d_in[5];
    const float* bf       = (const float*)d_in[6];
    const float* Ws       = (const float*)d_in[7];
    const float* bs       = (const float*)d_in[8];
    const float* bn_g     = (const float*)d_in[9];
    const float* bn_b     = (const float*)d_in[10];
    const float* ln_g     = (const float*)d_in[11];
    const float* ln_b     = (const float*)d_in[12];
    const float* lnout_g  = (const float*)d_in[13];
    const float* lnout_b  = (const float*)d_in[14];
    const float* W_fc     = (const float*)d_in[15];
    const float* b_fc     = (const float*)d_in[16];
    float* out = (float*)d_out;

    int* deg_p;        cudaGetSymbolAddress((void**)&deg_p, g_deg);
    float* stats_p;    cudaGetSymbolAddress((void**)&stats_p, g_stats);

    dim3 ggrid((N_NODES + GTM - 1) / GTM, 4);
    int nblocks = (N_NODES + 7) / 8;

    // Reordered so launch index 3 (the one ncu captures) is k_gemm layer 0.
    k_embed<<<(N_NODES * HID + 255) / 256, 256>>>(x, W_node, b_node);        // 0
    k_rbf<<<(N_EDGES * NUM_G + 255) / 256, 256>>>(dist);                     // 1
    k_zero_int<<<(N_NODES + 255) / 256, 256>>>(deg_p, N_NODES);              // 2
    k_gemm<<<ggrid, 256>>>(Wf, Ws, bf, bs);                                  // 3 (layer 0)
    k_hist<<<(N_EDGES + 255) / 256, 256>>>(ei);                              // 4
    k_scan<<<1, 1024>>>();                                                   // 5
    k_scatter<<<(N_EDGES + 255) / 256, 256>>>(ei);                           // 6

    for (int l = 0; l < N_LAYERS; l++) {
        const float* Wfl = Wf + (size_t)l * ZDIM * HID;
        const float* Wsl = Ws + (size_t)l * ZDIM * HID;
        k_zero_f<<<1, 256>>>(stats_p, 2 * HID);
        if (l > 0) k_gemm<<<ggrid, 256>>>(Wfl, Wsl, bf + l * HID, bs + l * HID);
        k_agg<<<nblocks, 256>>>(Wfl + 256 * HID, Wsl + 256 * HID);
        k_norm<<<nblocks, 256>>>(bn_g + l * HID, bn_b + l * HID,
                                 ln_g + l * HID, ln_b + l * HID);
    }
    k_out<<<nblocks, 256>>>(lnout_g, lnout_b, W_fc, b_fc, out);
}

// round 10
// speedup vs baseline: 1.4171x; 1.0108x over previous
#include <cuda_runtime.h>
#include <cuda_bf16.h>
#include <math.h>

#define N_NODES 20000
#define N_EDGES 320000
#define F_IN 6
#define HID 128
#define N_CLS 21
#define N_LAYERS 4
#define NUM_G 16
#define ZDIM 272
#define EPS 1e-5f
#define COEFF (-0.5f / ((8.0f/15.0f)*(8.0f/15.0f)))

typedef unsigned long long u64;

// ---- packed fp32x2 helpers (sm_103a FFMA2 path; PTX-only) ----
__device__ __forceinline__ u64 pack2(float lo, float hi) {
    u64 r; asm("mov.b64 %0, {%1, %2};" : "=l"(r) : "f"(lo), "f"(hi)); return r;
}
__device__ __forceinline__ void unpack2(u64 v, float& lo, float& hi) {
    asm("mov.b64 {%0, %1}, %2;" : "=f"(lo), "=f"(hi) : "l"(v));
}
__device__ __forceinline__ u64 fma2(u64 a, u64 b, u64 c) {
    u64 d; asm("fma.rn.f32x2 %0, %1, %2, %3;" : "=l"(d) : "l"(a), "l"(b), "l"(c)); return d;
}
__device__ __forceinline__ u64 add2(u64 a, u64 b) {
    u64 d; asm("add.rn.f32x2 %0, %1, %2;" : "=l"(d) : "l"(a), "l"(b)); return d;
}

// ------------- scratch -------------
__device__ float g_h[N_NODES * HID];
__device__ float g_AB[N_NODES * 512];
__device__ float g_e[N_EDGES * NUM_G];
__device__ float g_agg[N_NODES * HID];
__device__ float g_stats[2 * HID];
__device__ int   g_deg[N_NODES];
__device__ int   g_rowstart[N_NODES + 1];
__device__ int   g_cursor[N_NODES];
__device__ int   g_ssrc[N_EDGES];
__device__ int   g_seid[N_EDGES];

__device__ __forceinline__ float sigm(float x) {
    return __fdividef(1.f, 1.f + __expf(-x));
}
__device__ __forceinline__ float splus(float x) {
    float e = __expf(-fabsf(x));
    return fmaxf(x, 0.f) + __logf(1.f + e);
}

// ------------- tiny utility kernels -------------
__global__ void k_zero_int(int* p, int n) {
    int i = blockIdx.x * blockDim.x + threadIdx.x;
    if (i < n) p[i] = 0;
}
__global__ void k_zero_f(float* p, int n) {
    int i = blockIdx.x * blockDim.x + threadIdx.x;
    if (i < n) p[i] = 0.f;
}

__global__ __launch_bounds__(256) void k_embed(const float* __restrict__ x,
                                               const float* __restrict__ W,
                                               const float* __restrict__ b) {
    int t = blockIdx.x * blockDim.x + threadIdx.x;
    if (t >= N_NODES * HID) return;
    int n = t >> 7, c = t & 127;
    float acc = b[c];
    #pragma unroll
    for (int k = 0; k < F_IN; k++) acc += x[n * F_IN + k] * W[k * HID + c];
    g_h[t] = acc;
}

__global__ __launch_bounds__(256) void k_rbf(const float* __restrict__ dist) {
    int t = blockIdx.x * blockDim.x + threadIdx.x;
    if (t >= N_EDGES * NUM_G) return;
    int e = t >> 4, k = t & 15;
    float u = dist[e] - (float)k * (8.0f / 15.0f);
    g_e[t] = __expf(COEFF * u * u);
}

__global__ __launch_bounds__(256) void k_hist(const int* __restrict__ ei) {
    int i = blockIdx.x * blockDim.x + threadIdx.x;
    if (i >= N_EDGES) return;
    atomicAdd(&g_deg[ei[N_EDGES + i]], 1);
}

// warp-shuffle block scan over degrees -> rowstart, cursor
__global__ __launch_bounds__(1024) void k_scan() {
    __shared__ int wsum[32];
    __shared__ int carry_s;
    int tid = threadIdx.x, lane = tid & 31, wid = tid >> 5;
    if (tid == 0) { carry_s = 0; g_rowstart[0] = 0; }
    __syncthreads();
    for (int base = 0; base < N_NODES; base += 1024) {
        int i = base + tid;
        int v = (i < N_NODES) ? g_deg[i] : 0;
        int x = v;
        #pragma unroll
        for (int off = 1; off < 32; off <<= 1) {
            int y = __shfl_up_sync(0xffffffffu, x, off);
            if (lane >= off) x += y;
        }
        if (lane == 31) wsum[wid] = x;
        __syncthreads();
        if (wid == 0) {
            int s = wsum[lane];
            #pragma unroll
            for (int off = 1; off < 32; off <<= 1) {
                int y = __shfl_up_sync(0xffffffffu, s, off);
                if (lane >= off) s += y;
            }
            wsum[lane] = s;
        }
        __syncthreads();
        int c = carry_s;
        int incl = x + ((wid > 0) ? wsum[wid - 1] : 0) + c;
        if (i < N_NODES) {
            g_rowstart[i + 1] = incl;
            g_cursor[i] = incl - v;
        }
        int total = wsum[31];
        __syncthreads();
        if (tid == 0) carry_s = c + total;
        __syncthreads();
    }
}

__global__ __launch_bounds__(256) void k_scatter(const int* __restrict__ ei) {
    int i = blockIdx.x * blockDim.x + threadIdx.x;
    if (i >= N_EDGES) return;
    int dst = ei[N_EDGES + i];
    int pos = atomicAdd(&g_cursor[dst], 1);
    g_ssrc[pos] = ei[i];
    g_seid[pos] = i;
}

// ------------- node GEMM: AB = h @ Wcat + bias (FFMA2, dbl-buffered smem) ----
#define GTM 128
#define GTN 128
#define GTK 16
__global__ __launch_bounds__(256, 2) void k_gemm(const float* __restrict__ Wf,
                                                 const float* __restrict__ Ws,
                                                 const float* __restrict__ bf,
                                                 const float* __restrict__ bs) {
    __shared__ float As[2][GTK][GTM + 4];
    __shared__ float Bs[2][GTK][GTN];
    int tid = threadIdx.x;
    int m0 = blockIdx.x * GTM;
    int g = blockIdx.y;  // 0..3
    const float* __restrict__ Wsrc = (g < 2) ? Wf : Ws;
    int rowoff = (g & 1) * 128;
    int tx = tid & 15, ty = tid >> 4;

    int lm = tid & 127;
    int lk = (tid >> 7) * 8;     // 0 or 8
    int brow = tid >> 4;         // 0..15
    int bcol = (tid & 15) * 8;

    u64 C2[8][4];
    #pragma unroll
    for (int i = 0; i < 8; i++)
        #pragma unroll
        for (int j = 0; j < 4; j++) C2[i][j] = 0ull;

    float4 av0, av1, bv0, bv1;
    int gm = m0 + lm;
    // prologue: tile 0
    {
        av0 = make_float4(0.f, 0.f, 0.f, 0.f); av1 = av0;
        if (gm < N_NODES) {
            av0 = *(const float4*)&g_h[gm * HID + lk];
            av1 = *(const float4*)&g_h[gm * HID + lk + 4];
        }
        bv0 = *(const float4*)&Wsrc[(rowoff + brow) * HID + bcol];
        bv1 = *(const float4*)&Wsrc[(rowoff + brow) * HID + bcol + 4];
        As[0][lk + 0][lm] = av0.x; As[0][lk + 1][lm] = av0.y;
        As[0][lk + 2][lm] = av0.z; As[0][lk + 3][lm] = av0.w;
        As[0][lk + 4][lm] = av1.x; As[0][lk + 5][lm] = av1.y;
        As[0][lk + 6][lm] = av1.z; As[0][lk + 7][lm] = av1.w;
        *(float4*)&Bs[0][brow][bcol]     = bv0;
        *(float4*)&Bs[0][brow][bcol + 4] = bv1;
    }
    __syncthreads();

    #pragma unroll
    for (int t = 0; t < 8; t++) {
        int stage = t & 1;
        if (t < 7) {
            int kc = (t + 1) * GTK;
            av0 = make_float4(0.f, 0.f, 0.f, 0.f); av1 = av0;
            if (gm < N_NODES) {
                av0 = *(const float4*)&g_h[gm * HID + kc + lk];
                av1 = *(const float4*)&g_h[gm * HID + kc + lk + 4];
            }
            bv0 = *(const float4*)&Wsrc[(rowoff + kc + brow) * HID + bcol];
            bv1 = *(const float4*)&Wsrc[(rowoff + kc + brow) * HID + bcol + 4];
        }
        #pragma unroll
        for (int k = 0; k < GTK; k++) {
            float a[8];
            *(float4*)(a + 0) = *(float4*)&As[stage][k][ty * 8];
            *(float4*)(a + 4) = *(float4*)&As[stage][k][ty * 8 + 4];
            ulonglong2 b0 = *(ulonglong2*)&Bs[stage][k][tx * 8];
            ulonglong2 b1 = *(ulonglong2*)&Bs[stage][k][tx * 8 + 4];
            u64 bp[4] = {b0.x, b0.y, b1.x, b1.y};
            #pragma unroll
            for (int i = 0; i < 8; i++) {
                u64 ap = pack2(a[i], a[i]);
                #pragma unroll
                for (int j = 0; j < 4; j++)
                    C2[i][j] = fma2(ap, bp[j], C2[i][j]);
            }
        }
        if (t < 7) {
            int ns = stage ^ 1;
            As[ns][lk + 0][lm] = av0.x; As[ns][lk + 1][lm] = av0.y;
            As[ns][lk + 2][lm] = av0.z; As[ns][lk + 3][lm] = av0.w;
            As[ns][lk + 4][lm] = av1.x; As[ns][lk + 5][lm] = av1.y;
            As[ns][lk + 6][lm] = av1.z; As[ns][lk + 7][lm] = av1.w;
            *(float4*)&Bs[ns][brow][bcol]     = bv0;
            *(float4*)&Bs[ns][brow][bcol + 4] = bv1;
            __syncthreads();
        }
    }

    float bias[8];
    #pragma unroll
    for (int j = 0; j < 8; j++) bias[j] = 0.f;
    if (g == 0) {
        *(float4*)(bias + 0) = *(const float4*)&bf[tx * 8];
        *(float4*)(bias + 4) = *(const float4*)&bf[tx * 8 + 4];
    } else if (g == 2) {
        *(float4*)(bias + 0) = *(const float4*)&bs[tx * 8];
        *(float4*)(bias + 4) = *(const float4*)&bs[tx * 8 + 4];
    }
    #pragma unroll
    for (int i = 0; i < 8; i++) {
        int om = m0 + ty * 8 + i;
        if (om < N_NODES) {
            float o[8];
            #pragma unroll
            for (int j = 0; j < 4; j++) {
                float lo, hi;
                unpack2(C2[i][j], lo, hi);
                o[2 * j] = lo + bias[2 * j];
                o[2 * j + 1] = hi + bias[2 * j + 1];
            }
            *(float4*)&g_AB[om * 512 + g * 128 + tx * 8]     = *(float4*)(o + 0);
            *(float4*)&g_AB[om * 512 + g * 128 + tx * 8 + 4] = *(float4*)(o + 4);
        }
    }
}

// ------------- per-node aggregation: pipelined 4-edge groups -------------
__global__ __launch_bounds__(256, 2) void k_agg(const float* __restrict__ Wfe,
                                                const float* __restrict__ Wse) {
    __shared__ ulonglong2 sWf[NUM_G][32];
    __shared__ ulonglong2 sWs[NUM_G][32];
    __shared__ float sSum[HID], sSq[HID];
    int tid = threadIdx.x;
    for (int i = tid; i < NUM_G * 32; i += 256) {
        ((ulonglong2*)sWf)[i] = ((const ulonglong2*)Wfe)[i];
        ((ulonglong2*)sWs)[i] = ((const ulonglong2*)Wse)[i];
    }
    if (tid < HID) { sSum[tid] = 0.f; sSq[tid] = 0.f; }
    __syncthreads();

    int warp = tid >> 5, lane = tid & 31;
    int node = blockIdx.x * 8 + warp;
    float acc0 = 0.f, acc1 = 0.f, acc2 = 0.f, acc3 = 0.f;
    if (node < N_NODES) {
        ulonglong2 Afp = *(const ulonglong2*)&g_AB[node * 512 + lane * 4];
        ulonglong2 Asp = *(const ulonglong2*)&g_AB[node * 512 + 256 + lane * 4];
        int p0 = g_rowstart[node], p1 = g_rowstart[node + 1];
        int ngroups = (p1 - p0 + 3) >> 2;
        int cs[4]; float cev[4];
        if (ngroups > 0) {
            #pragma unroll
            for (int e = 0; e < 4; e++) {
                int q = min(p0 + e, p1 - 1);
                cs[e] = g_ssrc[q];
                int eid = g_seid[q];
                cev[e] = g_e[eid * NUM_G + (lane & 15)];
            }
        }
        for (int gi = 0; gi < ngroups; gi++) {
            int p = p0 + gi * 4;
            // issue this group's gathers (consumed after the rank loop)
            ulonglong2 bf4[4], bs4[4];
            #pragma unroll
            for (int e = 0; e < 4; e++) {
                bf4[e] = *(const ulonglong2*)&g_AB[cs[e] * 512 + 128 + lane * 4];
                bs4[e] = *(const ulonglong2*)&g_AB[cs[e] * 512 + 384 + lane * 4];
            }
            // prefetch next group's indices + RBF values
            int ns[4]; float nev[4];
            if (gi + 1 < ngroups) {
                int np = p + 4;
                #pragma unroll
                for (int e = 0; e < 4; e++) {
                    int q = min(np + e, p1 - 1);
                    ns[e] = g_ssrc[q];
                    int eid = g_seid[q];
                    nev[e] = g_e[eid * NUM_G + (lane & 15)];
                }
            }
            // rank-16 RBF accumulation (smem weights only)
            u64 rf[4][2], rs[4][2];
            #pragma unroll
            for (int e = 0; e < 4; e++) {
                rf[e][0] = rf[e][1] = 0ull;
                rs[e][0] = rs[e][1] = 0ull;
            }
            #pragma unroll
            for (int k = 0; k < NUM_G; k++) {
                ulonglong2 wf = sWf[k][lane];
                ulonglong2 ws = sWs[k][lane];
                #pragma unroll
                for (int e = 0; e < 4; e++) {
                    float ek = __shfl_sync(0xffffffffu, cev[e], k);
                    u64 ekp = pack2(ek, ek);
                    rf[e][0] = fma2(ekp, wf.x, rf[e][0]);
                    rf[e][1] = fma2(ekp, wf.y, rf[e][1]);
                    rs[e][0] = fma2(ekp, ws.x, rs[e][0]);
                    rs[e][1] = fma2(ekp, ws.y, rs[e][1]);
                }
            }
            // combine with gathers (latency now hidden) + nonlinearity
            #pragma unroll
            for (int e = 0; e < 4; e++) {
                u64 fp0 = add2(add2(Afp.x, bf4[e].x), rf[e][0]);
                u64 fp1 = add2(add2(Afp.y, bf4[e].y), rf[e][1]);
                u64 sp0 = add2(add2(Asp.x, bs4[e].x), rs[e][0]);
                u64 sp1 = add2(add2(Asp.y, bs4[e].y), rs[e][1]);
                float f0, f1, f2, f3, s0, s1, s2, s3;
                unpack2(fp0, f0, f1); unpack2(fp1, f2, f3);
                unpack2(sp0, s0, s1); unpack2(sp1, s2, s3);
                float m = (p + e < p1) ? 1.f : 0.f;
                acc0 += m * sigm(f0) * splus(s0);
                acc1 += m * sigm(f1) * splus(s1);
                acc2 += m * sigm(f2) * splus(s2);
                acc3 += m * sigm(f3) * splus(s3);
            }
            #pragma unroll
            for (int e = 0; e < 4; e++) { cs[e] = ns[e]; cev[e] = nev[e]; }
        }
        float4 o = make_float4(acc0, acc1, acc2, acc3);
        *(float4*)&g_agg[node * HID + lane * 4] = o;
    }
    int c = lane * 4;
    atomicAdd(&sSum[c + 0], acc0); atomicAdd(&sSq[c + 0], acc0 * acc0);
    atomicAdd(&sSum[c + 1], acc1); atomicAdd(&sSq[c + 1], acc1 * acc1);
    atomicAdd(&sSum[c + 2], acc2); atomicAdd(&sSq[c + 2], acc2 * acc2);
    atomicAdd(&sSum[c + 3], acc3); atomicAdd(&sSq[c + 3], acc3 * acc3);
    __syncthreads();
    if (tid < HID) {
        atomicAdd(&g_stats[tid], sSum[tid]);
        atomicAdd(&g_stats[HID + tid], sSq[tid]);
    }
}

// ------------- BN + residual + LN + ReLU + residual -------------
__global__ __launch_bounds__(256) void k_norm(const float* __restrict__ bng,
                                              const float* __restrict__ bnb,
                                              const float* __restrict__ lng,
                                              const float* __restrict__ lnb) {
    int warp = threadIdx.x >> 5, lane = threadIdx.x & 31;
    int node = blockIdx.x * 8 + warp;
    if (node >= N_NODES) return;
    const float invN = 1.f / (float)N_NODES;
    float4 a = *(const float4*)&g_agg[node * HID + lane * 4];
    float4 hv = *(const float4*)&g_h[node * HID + lane * 4];
    float av[4] = {a.x, a.y, a.z, a.w};
    float hvv[4] = {hv.x, hv.y, hv.z, hv.w};
    float c[4];
    #pragma unroll
    for (int i = 0; i < 4; i++) {
        int ch = lane * 4 + i;
        float mu = g_stats[ch] * invN;
        float var = g_stats[HID + ch] * invN - mu * mu;
        float an = (av[i] - mu) * rsqrtf(var + EPS) * bng[ch] + bnb[ch];
        c[i] = an + hvv[i];
    }
    float s1 = c[0] + c[1] + c[2] + c[3];
    float s2 = c[0]*c[0] + c[1]*c[1] + c[2]*c[2] + c[3]*c[3];
    #pragma unroll
    for (int off = 16; off > 0; off >>= 1) {
        s1 += __shfl_xor_sync(0xffffffffu, s1, off);
        s2 += __shfl_xor_sync(0xffffffffu, s2, off);
    }
    float m = s1 * (1.f / HID);
    float r = rsqrtf(s2 * (1.f / HID) - m * m + EPS);
    float out[4];
    #pragma unroll
    for (int i = 0; i < 4; i++) {
        int ch = lane * 4 + i;
        out[i] = fmaxf((c[i] - m) * r * lng[ch] + lnb[ch], 0.f) + hvv[i];
    }
    float4 o = make_float4(out[0], out[1], out[2], out[3]);
    *(float4*)&g_h[node * HID + lane * 4] = o;
}

// ------------- final LN + FC -------------
__global__ __launch_bounds__(256) void k_out(const float* __restrict__ lg,
                                             const float* __restrict__ lb,
                                             const float* __restrict__ Wfc,
                                             const float* __restrict__ bfc,
                                             float* __restrict__ out) {
    int warp = threadIdx.x >> 5, lane = threadIdx.x & 31;
    int node = blockIdx.x * 8 + warp;
    if (node >= N_NODES) return;
    float4 hv = *(const float4*)&g_h[node * HID + lane * 4];
    float h[4] = {hv.x, hv.y, hv.z, hv.w};
    float s1 = h[0] + h[1] + h[2] + h[3];
    float s2 = h[0]*h[0] + h[1]*h[1] + h[2]*h[2] + h[3]*h[3];
    #pragma unroll
    for (int off = 16; off > 0; off >>= 1) {
        s1 += __shfl_xor_sync(0xffffffffu, s1, off);
        s2 += __shfl_xor_sync(0xffffffffu, s2, off);
    }
    float m = s1 * (1.f / HID);
    float r = rsqrtf(s2 * (1.f / HID) - m * m + EPS);
    float hn[4];
    #pragma unroll
    for (int i = 0; i < 4; i++) {
        int ch = lane * 4 + i;
        hn[i] = (h[i] - m) * r * lg[ch] + lb[ch];
    }
    for (int cidx = 0; cidx < N_CLS; cidx++) {
        float p = hn[0] * Wfc[(lane * 4 + 0) * N_CLS + cidx]
                + hn[1] * Wfc[(lane * 4 + 1) * N_CLS + cidx]
                + hn[2] * Wfc[(lane * 4 + 2) * N_CLS + cidx]
                + hn[3] * Wfc[(lane * 4 + 3) * N_CLS + cidx];
        #pragma unroll
        for (int off = 16; off > 0; off >>= 1)
            p += __shfl_xor_sync(0xffffffffu, p, off);
        if (lane == 0) out[node * N_CLS + cidx] = p + bfc[cidx];
    }
}

// ------------- launch -------------
extern "C" void kernel_launch(void* const* d_in, const int* in_sizes, int n_in,
                              void* d_out, int out_size) {
    const float* x        = (const float*)d_in[0];
    const int*   ei       = (const int*)d_in[1];
    const float* dist     = (const float*)d_in[2];
    const float* W_node   = (const float*)d_in[3];
    const float* b_node   = (const float*)d_in[4];
    const float* Wf       = (const float*)d_in[5];
    const float* bf       = (const float*)d_in[6];
    const float* Ws       = (const float*)d_in[7];
    const float* bs       = (const float*)d_in[8];
    const float* bn_g     = (const float*)d_in[9];
    const float* bn_b     = (const float*)d_in[10];
    const float* ln_g     = (const float*)d_in[11];
    const float* ln_b     = (const float*)d_in[12];
    const float* lnout_g  = (const float*)d_in[13];
    const float* lnout_b  = (const float*)d_in[14];
    const float* W_fc     = (const float*)d_in[15];
    const float* b_fc     = (const float*)d_in[16];
    float* out = (float*)d_out;

    int* deg_p;        cudaGetSymbolAddress((void**)&deg_p, g_deg);
    float* stats_p;    cudaGetSymbolAddress((void**)&stats_p, g_stats);

    dim3 ggrid((N_NODES + GTM - 1) / GTM, 4);
    int nblocks = (N_NODES + 7) / 8;

    // k_gemm kept at launch index 3 (the ncu-captured slot).
    k_embed<<<(N_NODES * HID + 255) / 256, 256>>>(x, W_node, b_node);        // 0
    k_rbf<<<(N_EDGES * NUM_G + 255) / 256, 256>>>(dist);                     // 1
    k_zero_int<<<(N_NODES + 255) / 256, 256>>>(deg_p, N_NODES);              // 2
    k_gemm<<<ggrid, 256>>>(Wf, Ws, bf, bs);                                  // 3 (layer 0)
    k_hist<<<(N_EDGES + 255) / 256, 256>>>(ei);                              // 4
    k_scan<<<1, 1024>>>();                                                   // 5
    k_scatter<<<(N_EDGES + 255) / 256, 256>>>(ei);                           // 6

    for (int l = 0; l < N_LAYERS; l++) {
        const float* Wfl = Wf + (size_t)l * ZDIM * HID;
        const float* Wsl = Ws + (size_t)l * ZDIM * HID;
        k_zero_f<<<1, 256>>>(stats_p, 2 * HID);
        if (l > 0) k_gemm<<<ggrid, 256>>>(Wfl, Wsl, bf + l * HID, bs + l * HID);
        k_agg<<<nblocks, 256>>>(Wfl + 256 * HID, Wsl + 256 * HID);
        k_norm<<<nblocks, 256>>>(bn_g + l * HID, bn_b + l * HID,
                                 ln_g + l * HID, ln_b + l * HID);
    }
    k_out<<<nblocks, 256>>>(lnout_g, lnout_b, W_fc, b_fc, out);
}